// round 16
// baseline (speedup 1.0000x reference)
#include <cuda_runtime.h>
#include <cuda_bf16.h>
#include <math.h>
#include <stdint.h>

typedef __nv_bfloat16  bf16;
typedef __nv_bfloat162 bf162;

// ---------------- problem dims (fixed) ----------------
#define BB 2
#define SS 2048
#define HH 1024
#define II 2048
#define EE 8
#define NHH 16
#define DD 64
#define TT (BB*SS)   // 4096
#define QKVS 3072

// ---------------- device scratch ----------------
__device__ bf16  g_y   [TT*HH];
__device__ bf16  g_qkv [(size_t)TT*QKVS];
__device__ bf16  g_wqkv[(size_t)QKVS*HH];
__device__ bf16  g_woh [(size_t)HH*HH];
__device__ bf16  g_w1h [(size_t)EE*II*HH];
__device__ bf16  g_w2h [(size_t)EE*HH*II];
__device__ bf16  g_w3h [(size_t)EE*II*HH];
__device__ bf16  g_vT  [(size_t)BB*NHH*DD*SS];
__device__ bf16  g_att [TT*HH];
__device__ bf16  g_y2h [TT*HH];
__device__ float g_y2f [TT*HH];
__device__ bf16  g_h1  [(size_t)EE*TT*II];
__device__ bf16  g_h3  [(size_t)EE*TT*II];
__device__ float g_moe [(size_t)EE*TT*HH];   // weighted expert partials (f32)
__device__ int   g_cnt [EE];
__device__ int   g_tok [EE*TT];
__device__ float g_wgt [EE*TT];
__device__ int   g_slot[2*TT];               // token -> (e*TT+pos) x2

// ---------------- helpers ----------------
__device__ __forceinline__ void mma_bf16(float* c, const unsigned* a, const unsigned* b) {
    asm volatile(
        "mma.sync.aligned.m16n8k16.row.col.f32.bf16.bf16.f32 "
        "{%0,%1,%2,%3}, {%4,%5,%6,%7}, {%8,%9}, {%0,%1,%2,%3};"
        : "+f"(c[0]), "+f"(c[1]), "+f"(c[2]), "+f"(c[3])
        : "r"(a[0]), "r"(a[1]), "r"(a[2]), "r"(a[3]),
          "r"(b[0]), "r"(b[1]));
}
__device__ __forceinline__ void ldsm4(unsigned* r, unsigned addr) {
    asm volatile("ldmatrix.sync.aligned.m8n8.x4.shared.b16 {%0,%1,%2,%3}, [%4];"
        : "=r"(r[0]), "=r"(r[1]), "=r"(r[2]), "=r"(r[3]) : "r"(addr));
}
__device__ __forceinline__ void cp16h(bf16* dst, const bf16* src, int bytes) {
    unsigned d = (unsigned)__cvta_generic_to_shared(dst);
    asm volatile("cp.async.cg.shared.global [%0], [%1], 16, %2;"
                 :: "r"(d), "l"(src), "r"(bytes));
}
#define CP_COMMIT() asm volatile("cp.async.commit_group;")
#define CP_WAIT1()  asm volatile("cp.async.wait_group 1;")
#define CP_WAIT2()  asm volatile("cp.async.wait_group 2;")

// ---------------- fp32 -> bf16 weight conversion ----------------
__global__ void cvt_kernel(bf16* __restrict__ dst, const float* __restrict__ src, int n) {
    int i = (blockIdx.x * 256 + threadIdx.x) * 4;
    if (i < n) {
        float4 v = *reinterpret_cast<const float4*>(src + i);
        bf162* d = reinterpret_cast<bf162*>(dst + i);
        d[0] = __floats2bfloat162_rn(v.x, v.y);
        d[1] = __floats2bfloat162_rn(v.z, v.w);
    }
}

// ---------------- zero counters ----------------
__global__ void zero_cnt_kernel() {
    if (threadIdx.x < EE) g_cnt[threadIdx.x] = 0;
}

// ---------------- rmsnorm (fp32 in; bf16 out, optional fp32 copy) ----------------
__global__ void rmsnorm_kernel(const float* __restrict__ x,
                               const float* __restrict__ w,
                               bf16* __restrict__ y, float* __restrict__ yf) {
    int t = blockIdx.x;
    const float* xr = x + (size_t)t * HH;
    float ss = 0.f;
    for (int d = threadIdx.x; d < HH; d += 256) { float v = xr[d]; ss += v * v; }
    __shared__ float red[256];
    red[threadIdx.x] = ss;
    __syncthreads();
    for (int s = 128; s > 0; s >>= 1) {
        if (threadIdx.x < s) red[threadIdx.x] += red[threadIdx.x + s];
        __syncthreads();
    }
    float rms = rsqrtf(red[0] * (1.0f / HH) + 1e-5f);
    for (int d = threadIdx.x; d < HH; d += 256) {
        float v = xr[d] * rms * w[d];
        y[(size_t)t * HH + d] = __float2bfloat16_rn(v);
        if (yf) yf[(size_t)t * HH + d] = v;
    }
}

// ---------------- bf16 GEMM v5: 256x128 CTA tile, 8 warps, 4-stage cp.async ----
// MODE 1: C(f32) = Res(f32) + A*B^T
// MODE 2: expert GEMM (gather A via g_tok), C bf16 + e*TT*N
// MODE 3: expert GEMM2 (A += e*TT*K), store weighted f32 partial to g_moe rows
// MODE 4: fused QKV — q/k bf16 into C; V blocks (n0>=2048) transposed into vT(=Res)
// MODE 5: expert w3 — C(bf16) = silu(Res=h1 bf16) * acc
#define PH     40                  // halves per row (80 B)
#define BM5    256
#define BN5    128
#define SSTR   ((BM5 + BN5) * PH)  // halves per stage
#define STAGES 4
#define GEMM_SMEM (STAGES * SSTR * 2)  // 122880 bytes

template <int MODE>
__device__ __forceinline__ void load_tile(
    bf16* As, bf16* Bs,
    const bf16* __restrict__ A, const bf16* __restrict__ Bm,
    const int* __restrict__ gidx,
    int m0, int n0, int Meff, int K, int k0, int lr, int lq) {
    // A: 256 rows x 4 chunks = 1024 chunks / 256 thr = 4 per thread
#pragma unroll
    for (int r = 0; r < 4; r++) {
        int row = lr + r * 64;
        int gm = m0 + row;
        const bf16* src = A + k0 + lq;
        int bytes = 0;
        if (gm < Meff) {
            long long ar = (MODE == 2 || MODE == 5) ? (long long)gidx[gm] : (long long)gm;
            src = A + ar * K + k0 + lq;
            bytes = 16;
        }
        cp16h(As + row * PH + lq, src, bytes);
    }
    // B: 128 rows x 4 chunks = 512 chunks -> 2 per thread
#pragma unroll
    for (int r = 0; r < 2; r++) {
        int row = lr + r * 64;
        cp16h(Bs + row * PH + lq, Bm + (size_t)(n0 + row) * K + k0 + lq, 16);
    }
}

template <int MODE>
__global__ __launch_bounds__(256, 1)
void tgemm(const bf16* __restrict__ A, const bf16* __restrict__ Bm,
           void* Cv, const void* Resv, int M, int N, int K) {
    int e = 0, Meff = M;
    const int* gidx = nullptr;
    if (MODE == 2 || MODE == 3 || MODE == 5) {
        e = blockIdx.z;
        Meff = g_cnt[e];
        Bm += (size_t)e * N * K;
        if (MODE == 2 || MODE == 5) gidx = g_tok + e * TT;
        else                        A += (size_t)e * TT * K;
    }
    int m0 = blockIdx.x * BM5, n0 = blockIdx.y * BN5;
    if (m0 >= Meff) return;

    extern __shared__ bf16 smh[];
    unsigned smu = (unsigned)__cvta_generic_to_shared(smh);

    int tid = threadIdx.x, lane = tid & 31, wid = tid >> 5;
    int wm = (wid & 3) * 64, wn = (wid >> 2) * 64;
    int g = lane >> 2, t = lane & 3;
    int lr = tid >> 2, lq = (tid & 3) * 8;

    int l7 = lane & 7, lb3 = (lane >> 3) & 1, lb4 = (lane >> 4) & 1;
    int laneA = (l7 + lb3 * 8) * PH + lb4 * 8;   // halves
    int laneB = (l7 + lb4 * 8) * PH + lb3 * 8;

    float acc[4][8][4];
#pragma unroll
    for (int mf = 0; mf < 4; mf++)
#pragma unroll
        for (int nf = 0; nf < 8; nf++)
#pragma unroll
            for (int i = 0; i < 4; i++) acc[mf][nf][i] = 0.f;

    const int NIT = K >> 5;   // BK = 32 halves

#pragma unroll
    for (int s = 0; s < STAGES - 1; s++) {
        bf16* As = smh + s * SSTR;
        load_tile<MODE>(As, As + BM5 * PH, A, Bm, gidx, m0, n0, Meff, K, s * 32, lr, lq);
        CP_COMMIT();
    }

    for (int it = 0; it < NIT; it++) {
        CP_WAIT2();
        __syncthreads();

        int pf = it + STAGES - 1;
        if (pf < NIT) {
            bf16* As = smh + (pf % STAGES) * SSTR;
            load_tile<MODE>(As, As + BM5 * PH, A, Bm, gidx, m0, n0, Meff, K, pf * 32, lr, lq);
        }
        CP_COMMIT();

        unsigned Au = smu + (unsigned)((it % STAGES) * SSTR) * 2u;
        unsigned Bu = Au + BM5 * PH * 2;
#pragma unroll
        for (int ks = 0; ks < 32; ks += 16) {
            unsigned a[4][4], b[8][2];
#pragma unroll
            for (int mf = 0; mf < 4; mf++)
                ldsm4(a[mf], Au + (unsigned)(((wm + mf * 16) * PH + ks) + laneA) * 2u);
#pragma unroll
            for (int np = 0; np < 4; np++)
                ldsm4(&b[2 * np][0], Bu + (unsigned)(((wn + np * 16) * PH + ks) + laneB) * 2u);
#pragma unroll
            for (int mf = 0; mf < 4; mf++)
#pragma unroll
                for (int nf = 0; nf < 8; nf++)
                    mma_bf16(acc[mf][nf], a[mf], b[nf]);
        }
        __syncthreads();
    }

    // ---- epilogue (C frag: rows g, g+8; cols 2t, 2t+1)
#pragma unroll
    for (int mf = 0; mf < 4; mf++) {
#pragma unroll
        for (int half = 0; half < 2; half++) {
            int m = m0 + wm + mf * 16 + g + half * 8;
            if (m >= Meff) continue;
            if (MODE == 3) {
                // weighted f32 partial, plain store (combined later)
                float* C = (float*)Cv + (size_t)(e * TT + m) * N;
                float w = g_wgt[e * TT + m];
#pragma unroll
                for (int nf = 0; nf < 8; nf++) {
                    int n = n0 + wn + nf * 8 + 2 * t;
                    C[n]     = acc[mf][nf][half * 2 + 0] * w;
                    C[n + 1] = acc[mf][nf][half * 2 + 1] * w;
                }
            } else if (MODE == 4) {
                if (n0 >= 2048) {
                    bf16* vT = (bf16*)const_cast<void*>(Resv);
                    int bb2 = m >> 11, ss2 = m & 2047;
#pragma unroll
                    for (int nf = 0; nf < 8; nf++) {
                        int nn = n0 + wn + nf * 8 + 2 * t - 2048;
                        int hh = nn >> 6, dd = nn & 63;
                        size_t base = (((size_t)bb2 * NHH + hh) * DD + dd) * SS + ss2;
                        vT[base]      = __float2bfloat16_rn(acc[mf][nf][half * 2 + 0]);
                        vT[base + SS] = __float2bfloat16_rn(acc[mf][nf][half * 2 + 1]);
                    }
                } else {
                    bf16* C = (bf16*)Cv;
#pragma unroll
                    for (int nf = 0; nf < 8; nf++) {
                        int n = n0 + wn + nf * 8 + 2 * t;
                        *reinterpret_cast<bf162*>(C + (size_t)m * N + n) =
                            __floats2bfloat162_rn(acc[mf][nf][half * 2 + 0],
                                                  acc[mf][nf][half * 2 + 1]);
                    }
                }
            } else if (MODE == 2) {
                bf16* C = (bf16*)Cv + (size_t)e * TT * N;
#pragma unroll
                for (int nf = 0; nf < 8; nf++) {
                    int n = n0 + wn + nf * 8 + 2 * t;
                    *reinterpret_cast<bf162*>(C + (size_t)m * N + n) =
                        __floats2bfloat162_rn(acc[mf][nf][half * 2 + 0],
                                              acc[mf][nf][half * 2 + 1]);
                }
            } else if (MODE == 5) {
                bf16* C = (bf16*)Cv + (size_t)e * TT * N;
                const bf16* R = (const bf16*)Resv + (size_t)e * TT * N;
#pragma unroll
                for (int nf = 0; nf < 8; nf++) {
                    int n = n0 + wn + nf * 8 + 2 * t;
                    bf162 hp = *reinterpret_cast<const bf162*>(R + (size_t)m * N + n);
                    float h0 = __bfloat162float(hp.x), h1v = __bfloat162float(hp.y);
                    float s0 = h0 / (1.f + __expf(-h0));
                    float s1 = h1v / (1.f + __expf(-h1v));
                    *reinterpret_cast<bf162*>(C + (size_t)m * N + n) =
                        __floats2bfloat162_rn(acc[mf][nf][half * 2 + 0] * s0,
                                              acc[mf][nf][half * 2 + 1] * s1);
                }
            } else {  // MODE 1
                float* C = (float*)Cv;
                const float* R = (const float*)Resv;
#pragma unroll
                for (int nf = 0; nf < 8; nf++) {
                    int n = n0 + wn + nf * 8 + 2 * t;
                    C[(size_t)m * N + n]     = acc[mf][nf][half * 2 + 0] + R[(size_t)m * N + n];
                    C[(size_t)m * N + n + 1] = acc[mf][nf][half * 2 + 1] + R[(size_t)m * N + n + 1];
                }
            }
        }
    }
}

// ---------------- flash attention, bf16 mma (unchanged from R14) ----------------
#define APH 72
#define ATTN_SMEM ((64 + 128 + 128 + 64) * APH * 2)   // 55296 bytes

__global__ __launch_bounds__(128, 3)
void attn_tc(const bf16* __restrict__ QKV, const bf16* __restrict__ VT,
             bf16* __restrict__ O) {
    extern __shared__ bf16 smh[];
    bf16* Qs = smh;
    bf16* Ks = Qs + 64 * APH;
    bf16* Vs = Ks + 128 * APH;
    bf16* Ps = Vs + 128 * APH;
    unsigned Qu = (unsigned)__cvta_generic_to_shared(Qs);
    unsigned Ku = (unsigned)__cvta_generic_to_shared(Ks);
    unsigned Vu = (unsigned)__cvta_generic_to_shared(Vs);
    unsigned Pu = (unsigned)__cvta_generic_to_shared(Ps);

    int qt = blockIdx.x, h = blockIdx.y, b = blockIdx.z;
    int tid = threadIdx.x, lane = tid & 31, wid = tid >> 5;
    int g = lane >> 2, t = lane & 3;
    int hoff = h * DD;

    int l7 = lane & 7, lb3 = (lane >> 3) & 1, lb4 = (lane >> 4) & 1;
    int laneA = (l7 + lb3 * 8) * APH + lb4 * 8;
    int laneB = (l7 + lb4 * 8) * APH + lb3 * 8;

    const bf16* Q  = QKV + hoff;
    const bf16* Kp = QKV + 1024 + hoff;
    const bf16* Vt = VT + ((size_t)b * NHH + h) * DD * SS;

#pragma unroll
    for (int j = 0; j < 4; j++) {
        int i = tid + j * 128;
        int r = i >> 3, c = (i & 7) * 8;
        cp16h(Qs + r * APH + c, Q + (size_t)(b * SS + qt * 64 + r) * QKVS + c, 16);
    }

    auto ldkv = [&](int kt, int bf) {
#pragma unroll
        for (int j = 0; j < 4; j++) {
            int i = tid + j * 128;
            int r = i >> 3, c = (i & 7) * 8;
            cp16h(Ks + bf * 64 * APH + r * APH + c,
                  Kp + (size_t)(b * SS + kt * 64 + r) * QKVS + c, 16);
        }
#pragma unroll
        for (int j = 0; j < 4; j++) {
            int i = tid + j * 128;
            int r = i >> 3, c = (i & 7) * 8;
            cp16h(Vs + bf * 64 * APH + r * APH + c,
                  Vt + (size_t)r * SS + kt * 64 + c, 16);
        }
    };

    float oacc[8][4];
#pragma unroll
    for (int nf = 0; nf < 8; nf++)
#pragma unroll
        for (int i = 0; i < 4; i++) oacc[nf][i] = 0.f;
    float l0 = 0.f, l1 = 0.f;

    const int prow = wid * 16 + g;

    ldkv(0, 0);
    CP_COMMIT();

    for (int kt = 0; kt < SS / 64; kt++) {
        int bf = kt & 1;
        __syncthreads();
        if (kt + 1 < SS / 64) ldkv(kt + 1, bf ^ 1);
        CP_COMMIT();
        CP_WAIT1();
        __syncthreads();

        unsigned Kbu = Ku + (unsigned)(bf * 64 * APH) * 2u;
        unsigned Vbu = Vu + (unsigned)(bf * 64 * APH) * 2u;

        float sacc[8][4];
#pragma unroll
        for (int nf = 0; nf < 8; nf++)
#pragma unroll
            for (int i = 0; i < 4; i++) sacc[nf][i] = 0.f;
#pragma unroll
        for (int ks = 0; ks < 64; ks += 16) {
            unsigned a[4], bfr[8][2];
            ldsm4(a, Qu + (unsigned)((wid * 16 * APH + ks) + laneA) * 2u);
#pragma unroll
            for (int np = 0; np < 4; np++)
                ldsm4(&bfr[2 * np][0], Kbu + (unsigned)((np * 16 * APH + ks) + laneB) * 2u);
#pragma unroll
            for (int nf = 0; nf < 8; nf++)
                mma_bf16(sacc[nf], a, bfr[nf]);
        }

#pragma unroll
        for (int nf = 0; nf < 8; nf++) {
            float p0 = __expf(sacc[nf][0] * 0.125f);
            float p1 = __expf(sacc[nf][1] * 0.125f);
            float p2 = __expf(sacc[nf][2] * 0.125f);
            float p3 = __expf(sacc[nf][3] * 0.125f);
            l0 += p0 + p1; l1 += p2 + p3;
            *reinterpret_cast<bf162*>(Ps + prow * APH + nf * 8 + 2 * t) =
                __floats2bfloat162_rn(p0, p1);
            *reinterpret_cast<bf162*>(Ps + (prow + 8) * APH + nf * 8 + 2 * t) =
                __floats2bfloat162_rn(p2, p3);
        }
        __syncwarp();

#pragma unroll
        for (int ks = 0; ks < 64; ks += 16) {
            unsigned a[4], bfr[8][2];
            ldsm4(a, Pu + (unsigned)((wid * 16 * APH + ks) + laneA) * 2u);
#pragma unroll
            for (int np = 0; np < 4; np++)
                ldsm4(&bfr[2 * np][0], Vbu + (unsigned)((np * 16 * APH + ks) + laneB) * 2u);
#pragma unroll
            for (int nf = 0; nf < 8; nf++)
                mma_bf16(oacc[nf], a, bfr[nf]);
        }
    }

    l0 += __shfl_xor_sync(0xffffffffu, l0, 1);
    l0 += __shfl_xor_sync(0xffffffffu, l0, 2);
    l1 += __shfl_xor_sync(0xffffffffu, l1, 1);
    l1 += __shfl_xor_sync(0xffffffffu, l1, 2);
    float i0 = 1.f / l0, i1 = 1.f / l1;
    size_t rbase0 = ((size_t)(b * SS + qt * 64 + prow)) * HH + hoff;
    size_t rbase1 = rbase0 + (size_t)8 * HH;
#pragma unroll
    for (int nf = 0; nf < 8; nf++) {
        int c = nf * 8 + 2 * t;
        *reinterpret_cast<bf162*>(O + rbase0 + c) =
            __floats2bfloat162_rn(oacc[nf][0] * i0, oacc[nf][1] * i0);
        *reinterpret_cast<bf162*>(O + rbase1 + c) =
            __floats2bfloat162_rn(oacc[nf][2] * i1, oacc[nf][3] * i1);
    }
}

// ---------------- routing (fp32, exact) ----------------
__global__ void route_kernel(const float* __restrict__ y2,
                             const float* __restrict__ gw) {
    int t = blockIdx.x;
    int w = threadIdx.x >> 5, lane = threadIdx.x & 31;
    const float* xr = y2 + (size_t)t * HH;
    const float* gr = gw + (size_t)w * HH;
    float p = 0.f;
    for (int d = lane; d < HH; d += 32) p += xr[d] * gr[d];
#pragma unroll
    for (int o = 16; o > 0; o >>= 1) p += __shfl_down_sync(0xffffffffu, p, o);
    __shared__ float lg[EE];
    if (lane == 0) lg[w] = p;
    __syncthreads();
    if (threadIdx.x == 0) {
        int b0 = 0; float v0 = lg[0];
        for (int e = 1; e < EE; e++) if (lg[e] > v0) { v0 = lg[e]; b0 = e; }
        int b1 = -1; float v1 = -1e30f;
        for (int e = 0; e < EE; e++) {
            if (e == b0) continue;
            if (lg[e] > v1) { v1 = lg[e]; b1 = e; }
        }
        float ex = expf(v1 - v0);
        float den = 1.f / (1.f + ex);
        int p0 = atomicAdd(&g_cnt[b0], 1);
        g_tok[b0 * TT + p0] = t; g_wgt[b0 * TT + p0] = den;
        g_slot[2 * t] = b0 * TT + p0;
        int p1 = atomicAdd(&g_cnt[b1], 1);
        g_tok[b1 * TT + p1] = t; g_wgt[b1 * TT + p1] = ex * den;
        g_slot[2 * t + 1] = b1 * TT + p1;
    }
}

// ---------------- combine: out[t] += moe[slot0] + moe[slot1] ----------------
__global__ void combine_kernel(float* __restrict__ out,
                               const float* __restrict__ moe) {
    int t = blockIdx.x;
    int s0 = g_slot[2 * t], s1 = g_slot[2 * t + 1];
    int d = threadIdx.x * 4;
    float4 o = *reinterpret_cast<float4*>(out + (size_t)t * HH + d);
    float4 a = *reinterpret_cast<const float4*>(moe + (size_t)s0 * HH + d);
    float4 b = *reinterpret_cast<const float4*>(moe + (size_t)s1 * HH + d);
    o.x += a.x + b.x; o.y += a.y + b.y;
    o.z += a.z + b.z; o.w += a.w + b.w;
    *reinterpret_cast<float4*>(out + (size_t)t * HH + d) = o;
}

// ---------------- launch ----------------
extern "C" void kernel_launch(void* const* d_in, const int* in_sizes, int n_in,
                              void* d_out, int out_size) {
    const float* x   = (const float*)d_in[0];
    const float* ln1 = (const float*)d_in[1];
    const float* ln2 = (const float*)d_in[2];
    const float* wq  = (const float*)d_in[3];
    const float* wk  = (const float*)d_in[4];
    const float* wv  = (const float*)d_in[5];
    const float* wo  = (const float*)d_in[6];
    const float* gw  = (const float*)d_in[7];
    const float* w1  = (const float*)d_in[8];
    const float* w2  = (const float*)d_in[9];
    const float* w3  = (const float*)d_in[10];
    float* out = (float*)d_out;

    bf16 *y, *qkv, *wqkvh, *woh, *w1h, *w2h, *w3h, *vT, *att, *y2h, *h1, *h3;
    float *y2f, *moe;
    cudaGetSymbolAddress((void**)&y,     g_y);
    cudaGetSymbolAddress((void**)&qkv,   g_qkv);
    cudaGetSymbolAddress((void**)&wqkvh, g_wqkv);
    cudaGetSymbolAddress((void**)&woh,   g_woh);
    cudaGetSymbolAddress((void**)&w1h,   g_w1h);
    cudaGetSymbolAddress((void**)&w2h,   g_w2h);
    cudaGetSymbolAddress((void**)&w3h,   g_w3h);
    cudaGetSymbolAddress((void**)&vT,    g_vT);
    cudaGetSymbolAddress((void**)&att,   g_att);
    cudaGetSymbolAddress((void**)&y2h,   g_y2h);
    cudaGetSymbolAddress((void**)&y2f,   g_y2f);
    cudaGetSymbolAddress((void**)&h1,    g_h1);
    cudaGetSymbolAddress((void**)&h3,    g_h3);
    cudaGetSymbolAddress((void**)&moe,   g_moe);

    static int smem_set = 0;
    if (!smem_set) {
        cudaFuncSetAttribute(attn_tc,  cudaFuncAttributeMaxDynamicSharedMemorySize, ATTN_SMEM);
        cudaFuncSetAttribute(tgemm<1>, cudaFuncAttributeMaxDynamicSharedMemorySize, GEMM_SMEM);
        cudaFuncSetAttribute(tgemm<2>, cudaFuncAttributeMaxDynamicSharedMemorySize, GEMM_SMEM);
        cudaFuncSetAttribute(tgemm<3>, cudaFuncAttributeMaxDynamicSharedMemorySize, GEMM_SMEM);
        cudaFuncSetAttribute(tgemm<4>, cudaFuncAttributeMaxDynamicSharedMemorySize, GEMM_SMEM);
        cudaFuncSetAttribute(tgemm<5>, cudaFuncAttributeMaxDynamicSharedMemorySize, GEMM_SMEM);
        smem_set = 1;
    }

    zero_cnt_kernel<<<1, 32>>>();

    const int HW = HH * HH;
    const int EW = EE * II * HH;
    cvt_kernel<<<HW / 1024, 256>>>(wqkvh,          wq, HW);
    cvt_kernel<<<HW / 1024, 256>>>(wqkvh + HW,     wk, HW);
    cvt_kernel<<<HW / 1024, 256>>>(wqkvh + 2 * HW, wv, HW);
    cvt_kernel<<<HW / 1024, 256>>>(woh,            wo, HW);
    cvt_kernel<<<EW / 1024, 256>>>(w1h, w1, EW);
    cvt_kernel<<<EW / 1024, 256>>>(w2h, w2, EW);
    cvt_kernel<<<EW / 1024, 256>>>(w3h, w3, EW);

    // --- attention block ---
    rmsnorm_kernel<<<TT, 256>>>(x, ln1, y, nullptr);
    tgemm<4><<<dim3(TT / BM5, QKVS / BN5), 256, GEMM_SMEM>>>(y, wqkvh, qkv, vT, TT, QKVS, HH);
    attn_tc<<<dim3(SS / 64, NHH, BB), 128, ATTN_SMEM>>>(qkv, vT, att);
    tgemm<1><<<dim3(TT / BM5, HH / BN5), 256, GEMM_SMEM>>>(att, woh, out, x, TT, HH, HH);

    // --- MoE block ---
    rmsnorm_kernel<<<TT, 256>>>(out, ln2, y2h, y2f);
    route_kernel<<<TT, 256>>>(y2f, gw);
    tgemm<2><<<dim3(TT / BM5, II / BN5, EE), 256, GEMM_SMEM>>>(y2h, w1h, h1, nullptr, TT, II, HH);
    tgemm<5><<<dim3(TT / BM5, II / BN5, EE), 256, GEMM_SMEM>>>(y2h, w3h, h3, h1, TT, II, HH);
    tgemm<3><<<dim3(TT / BM5, HH / BN5, EE), 256, GEMM_SMEM>>>(h3, w2h, moe, nullptr, TT, HH, II);
    combine_kernel<<<TT, 256>>>(out, moe);
}

// round 17
// speedup vs baseline: 1.2124x; 1.2124x over previous
#include <cuda_runtime.h>
#include <cuda_bf16.h>
#include <math.h>
#include <stdint.h>

typedef __nv_bfloat16  bf16;
typedef __nv_bfloat162 bf162;

// ---------------- problem dims (fixed) ----------------
#define BB 2
#define SS 2048
#define HH 1024
#define II 2048
#define EE 8
#define NHH 16
#define DD 64
#define TT (BB*SS)   // 4096
#define QKVS 3072

// ---------------- device scratch ----------------
__device__ bf16  g_y   [TT*HH];
__device__ bf16  g_qkv [(size_t)TT*QKVS];
__device__ bf16  g_wqkv[(size_t)QKVS*HH];
__device__ bf16  g_woh [(size_t)HH*HH];
__device__ bf16  g_w1h [(size_t)EE*II*HH];
__device__ bf16  g_w2h [(size_t)EE*HH*II];
__device__ bf16  g_w3h [(size_t)EE*II*HH];
__device__ bf16  g_vT  [(size_t)BB*NHH*DD*SS];
__device__ bf16  g_att [TT*HH];
__device__ bf16  g_y2h [TT*HH];
__device__ float g_y2f [TT*HH];
__device__ bf16  g_h1  [(size_t)EE*TT*II];
__device__ bf16  g_h3  [(size_t)EE*TT*II];
__device__ float g_moe [(size_t)EE*TT*HH];   // weighted expert partials (f32)
__device__ int   g_cnt [EE];
__device__ int   g_tok [EE*TT];
__device__ float g_wgt [EE*TT];
__device__ int   g_slot[2*TT];               // token -> (e*TT+pos) x2

// ---------------- helpers ----------------
__device__ __forceinline__ void mma_bf16(float* c, const unsigned* a, const unsigned* b) {
    asm volatile(
        "mma.sync.aligned.m16n8k16.row.col.f32.bf16.bf16.f32 "
        "{%0,%1,%2,%3}, {%4,%5,%6,%7}, {%8,%9}, {%0,%1,%2,%3};"
        : "+f"(c[0]), "+f"(c[1]), "+f"(c[2]), "+f"(c[3])
        : "r"(a[0]), "r"(a[1]), "r"(a[2]), "r"(a[3]),
          "r"(b[0]), "r"(b[1]));
}
__device__ __forceinline__ void ldsm4(unsigned* r, unsigned addr) {
    asm volatile("ldmatrix.sync.aligned.m8n8.x4.shared.b16 {%0,%1,%2,%3}, [%4];"
        : "=r"(r[0]), "=r"(r[1]), "=r"(r[2]), "=r"(r[3]) : "r"(addr));
}
__device__ __forceinline__ void cp16h(bf16* dst, const bf16* src, int bytes) {
    unsigned d = (unsigned)__cvta_generic_to_shared(dst);
    asm volatile("cp.async.cg.shared.global [%0], [%1], 16, %2;"
                 :: "r"(d), "l"(src), "r"(bytes));
}
#define CP_COMMIT() asm volatile("cp.async.commit_group;")
#define CP_WAIT1()  asm volatile("cp.async.wait_group 1;")

// ---------------- fp32 -> bf16 weight conversion (8 elems/thread, 16B store) ----
__global__ void cvt_kernel(bf16* __restrict__ dst, const float* __restrict__ src, int n) {
    int i = (blockIdx.x * 256 + threadIdx.x) * 8;
    if (i < n) {
        float4 v0 = *reinterpret_cast<const float4*>(src + i);
        float4 v1 = *reinterpret_cast<const float4*>(src + i + 4);
        bf162 o[4];
        o[0] = __floats2bfloat162_rn(v0.x, v0.y);
        o[1] = __floats2bfloat162_rn(v0.z, v0.w);
        o[2] = __floats2bfloat162_rn(v1.x, v1.y);
        o[3] = __floats2bfloat162_rn(v1.z, v1.w);
        *reinterpret_cast<uint4*>(dst + i) = *reinterpret_cast<uint4*>(o);
    }
}

// ---------------- zero counters ----------------
__global__ void zero_cnt_kernel() {
    if (threadIdx.x < EE) g_cnt[threadIdx.x] = 0;
}

// ---------------- rmsnorm (fp32 in; bf16 out, optional fp32 copy) ----------------
__global__ void rmsnorm_kernel(const float* __restrict__ x,
                               const float* __restrict__ w,
                               bf16* __restrict__ y, float* __restrict__ yf) {
    int t = blockIdx.x;
    const float* xr = x + (size_t)t * HH;
    float ss = 0.f;
    for (int d = threadIdx.x; d < HH; d += 256) { float v = xr[d]; ss += v * v; }
    __shared__ float red[256];
    red[threadIdx.x] = ss;
    __syncthreads();
    for (int s = 128; s > 0; s >>= 1) {
        if (threadIdx.x < s) red[threadIdx.x] += red[threadIdx.x + s];
        __syncthreads();
    }
    float rms = rsqrtf(red[0] * (1.0f / HH) + 1e-5f);
    for (int d = threadIdx.x; d < HH; d += 256) {
        float v = xr[d] * rms * w[d];
        y[(size_t)t * HH + d] = __float2bfloat16_rn(v);
        if (yf) yf[(size_t)t * HH + d] = v;
    }
}

// ---------------- bf16 GEMM (R14 config): 128x128x32, 4 warps, 3-stage cp.async --
// MODE 1: C(f32) = Res(f32) + A*B^T
// MODE 2: expert GEMM (gather A via g_tok), C bf16 + e*TT*N
// MODE 3: expert GEMM2 (A += e*TT*K), store weighted f32 partial to g_moe rows
// MODE 4: fused QKV — q/k bf16 into C; V blocks (n0>=2048) transposed into vT(=Res)
// MODE 5: expert w3 — C(bf16) = silu(Res=h1 bf16) * acc
#define PH   40                   // halves per row (80 B)
#define SSTR (2 * 128 * PH)       // halves per stage
#define GEMM_SMEM (3 * SSTR * 2)  // 61440 bytes

template <int MODE>
__device__ __forceinline__ void load_tile(
    bf16* As, bf16* Bs,
    const bf16* __restrict__ A, const bf16* __restrict__ Bm,
    const int* __restrict__ gidx,
    int m0, int n0, int Meff, int K, int k0, int lr, int lq) {
#pragma unroll
    for (int r = 0; r < 4; r++) {
        int row = lr + r * 32;
        int gm = m0 + row;
        const bf16* src = A + k0 + lq;
        int bytes = 0;
        if (gm < Meff) {
            long long ar = (MODE == 2 || MODE == 5) ? (long long)gidx[gm] : (long long)gm;
            src = A + ar * K + k0 + lq;
            bytes = 16;
        }
        cp16h(As + row * PH + lq, src, bytes);
    }
#pragma unroll
    for (int r = 0; r < 4; r++) {
        int row = lr + r * 32;
        cp16h(Bs + row * PH + lq, Bm + (size_t)(n0 + row) * K + k0 + lq, 16);
    }
}

template <int MODE>
__global__ __launch_bounds__(128, 2)
void tgemm(const bf16* __restrict__ A, const bf16* __restrict__ Bm,
           void* Cv, const void* Resv, int M, int N, int K) {
    int e = 0, Meff = M;
    const int* gidx = nullptr;
    if (MODE == 2 || MODE == 3 || MODE == 5) {
        e = blockIdx.z;
        Meff = g_cnt[e];
        Bm += (size_t)e * N * K;
        if (MODE == 2 || MODE == 5) gidx = g_tok + e * TT;
        else                        A += (size_t)e * TT * K;
    }
    int m0 = blockIdx.x * 128, n0 = blockIdx.y * 128;
    if (m0 >= Meff) return;

    extern __shared__ bf16 smh[];
    unsigned smu = (unsigned)__cvta_generic_to_shared(smh);

    int tid = threadIdx.x, lane = tid & 31, wid = tid >> 5;
    int wm = (wid & 1) * 64, wn = (wid >> 1) * 64;
    int g = lane >> 2, t = lane & 3;
    int lr = tid >> 2, lq = (tid & 3) * 8;

    int l7 = lane & 7, lb3 = (lane >> 3) & 1, lb4 = (lane >> 4) & 1;
    int laneA = (l7 + lb3 * 8) * PH + lb4 * 8;   // halves
    int laneB = (l7 + lb4 * 8) * PH + lb3 * 8;

    float acc[4][8][4];
#pragma unroll
    for (int mf = 0; mf < 4; mf++)
#pragma unroll
        for (int nf = 0; nf < 8; nf++)
#pragma unroll
            for (int i = 0; i < 4; i++) acc[mf][nf][i] = 0.f;

    const int NIT = K >> 5;   // BK = 32 halves

#pragma unroll
    for (int s = 0; s < 2; s++) {
        bf16* As = smh + s * SSTR;
        load_tile<MODE>(As, As + 128 * PH, A, Bm, gidx, m0, n0, Meff, K, s * 32, lr, lq);
        CP_COMMIT();
    }

    for (int it = 0; it < NIT; it++) {
        CP_WAIT1();
        __syncthreads();

        int pf = it + 2;
        if (pf < NIT) {
            bf16* As = smh + (pf % 3) * SSTR;
            load_tile<MODE>(As, As + 128 * PH, A, Bm, gidx, m0, n0, Meff, K, pf * 32, lr, lq);
        }
        CP_COMMIT();

        unsigned Au = smu + (unsigned)((it % 3) * SSTR) * 2u;
        unsigned Bu = Au + 128 * PH * 2;
#pragma unroll
        for (int ks = 0; ks < 32; ks += 16) {
            unsigned a[4][4], b[8][2];
#pragma unroll
            for (int mf = 0; mf < 4; mf++)
                ldsm4(a[mf], Au + (unsigned)(((wm + mf * 16) * PH + ks) + laneA) * 2u);
#pragma unroll
            for (int np = 0; np < 4; np++)
                ldsm4(&b[2 * np][0], Bu + (unsigned)(((wn + np * 16) * PH + ks) + laneB) * 2u);
#pragma unroll
            for (int mf = 0; mf < 4; mf++)
#pragma unroll
                for (int nf = 0; nf < 8; nf++)
                    mma_bf16(acc[mf][nf], a[mf], b[nf]);
        }
        __syncthreads();
    }

    // ---- epilogue (C frag: rows g, g+8; cols 2t, 2t+1)
#pragma unroll
    for (int mf = 0; mf < 4; mf++) {
#pragma unroll
        for (int half = 0; half < 2; half++) {
            int m = m0 + wm + mf * 16 + g + half * 8;
            if (m >= Meff) continue;
            if (MODE == 3) {
                // weighted f32 partial, plain store (combined later)
                float* C = (float*)Cv + (size_t)(e * TT + m) * N;
                float w = g_wgt[e * TT + m];
#pragma unroll
                for (int nf = 0; nf < 8; nf++) {
                    int n = n0 + wn + nf * 8 + 2 * t;
                    C[n]     = acc[mf][nf][half * 2 + 0] * w;
                    C[n + 1] = acc[mf][nf][half * 2 + 1] * w;
                }
            } else if (MODE == 4) {
                if (n0 >= 2048) {
                    bf16* vT = (bf16*)const_cast<void*>(Resv);
                    int bb2 = m >> 11, ss2 = m & 2047;
#pragma unroll
                    for (int nf = 0; nf < 8; nf++) {
                        int nn = n0 + wn + nf * 8 + 2 * t - 2048;
                        int hh = nn >> 6, dd = nn & 63;
                        size_t base = (((size_t)bb2 * NHH + hh) * DD + dd) * SS + ss2;
                        vT[base]      = __float2bfloat16_rn(acc[mf][nf][half * 2 + 0]);
                        vT[base + SS] = __float2bfloat16_rn(acc[mf][nf][half * 2 + 1]);
                    }
                } else {
                    bf16* C = (bf16*)Cv;
#pragma unroll
                    for (int nf = 0; nf < 8; nf++) {
                        int n = n0 + wn + nf * 8 + 2 * t;
                        *reinterpret_cast<bf162*>(C + (size_t)m * N + n) =
                            __floats2bfloat162_rn(acc[mf][nf][half * 2 + 0],
                                                  acc[mf][nf][half * 2 + 1]);
                    }
                }
            } else if (MODE == 2) {
                bf16* C = (bf16*)Cv + (size_t)e * TT * N;
#pragma unroll
                for (int nf = 0; nf < 8; nf++) {
                    int n = n0 + wn + nf * 8 + 2 * t;
                    *reinterpret_cast<bf162*>(C + (size_t)m * N + n) =
                        __floats2bfloat162_rn(acc[mf][nf][half * 2 + 0],
                                              acc[mf][nf][half * 2 + 1]);
                }
            } else if (MODE == 5) {
                bf16* C = (bf16*)Cv + (size_t)e * TT * N;
                const bf16* R = (const bf16*)Resv + (size_t)e * TT * N;
#pragma unroll
                for (int nf = 0; nf < 8; nf++) {
                    int n = n0 + wn + nf * 8 + 2 * t;
                    bf162 hp = *reinterpret_cast<const bf162*>(R + (size_t)m * N + n);
                    float h0 = __bfloat162float(hp.x), h1v = __bfloat162float(hp.y);
                    float s0 = h0 / (1.f + __expf(-h0));
                    float s1 = h1v / (1.f + __expf(-h1v));
                    *reinterpret_cast<bf162*>(C + (size_t)m * N + n) =
                        __floats2bfloat162_rn(acc[mf][nf][half * 2 + 0] * s0,
                                              acc[mf][nf][half * 2 + 1] * s1);
                }
            } else {  // MODE 1
                float* C = (float*)Cv;
                const float* R = (const float*)Resv;
#pragma unroll
                for (int nf = 0; nf < 8; nf++) {
                    int n = n0 + wn + nf * 8 + 2 * t;
                    C[(size_t)m * N + n]     = acc[mf][nf][half * 2 + 0] + R[(size_t)m * N + n];
                    C[(size_t)m * N + n + 1] = acc[mf][nf][half * 2 + 1] + R[(size_t)m * N + n + 1];
                }
            }
        }
    }
}

// ---------------- flash attention, bf16 mma (R14, unchanged) ----------------
#define APH 72
#define ATTN_SMEM ((64 + 128 + 128 + 64) * APH * 2)   // 55296 bytes

__global__ __launch_bounds__(128, 3)
void attn_tc(const bf16* __restrict__ QKV, const bf16* __restrict__ VT,
             bf16* __restrict__ O) {
    extern __shared__ bf16 smh[];
    bf16* Qs = smh;
    bf16* Ks = Qs + 64 * APH;
    bf16* Vs = Ks + 128 * APH;
    bf16* Ps = Vs + 128 * APH;
    unsigned Qu = (unsigned)__cvta_generic_to_shared(Qs);
    unsigned Ku = (unsigned)__cvta_generic_to_shared(Ks);
    unsigned Vu = (unsigned)__cvta_generic_to_shared(Vs);
    unsigned Pu = (unsigned)__cvta_generic_to_shared(Ps);

    int qt = blockIdx.x, h = blockIdx.y, b = blockIdx.z;
    int tid = threadIdx.x, lane = tid & 31, wid = tid >> 5;
    int g = lane >> 2, t = lane & 3;
    int hoff = h * DD;

    int l7 = lane & 7, lb3 = (lane >> 3) & 1, lb4 = (lane >> 4) & 1;
    int laneA = (l7 + lb3 * 8) * APH + lb4 * 8;
    int laneB = (l7 + lb4 * 8) * APH + lb3 * 8;

    const bf16* Q  = QKV + hoff;
    const bf16* Kp = QKV + 1024 + hoff;
    const bf16* Vt = VT + ((size_t)b * NHH + h) * DD * SS;

#pragma unroll
    for (int j = 0; j < 4; j++) {
        int i = tid + j * 128;
        int r = i >> 3, c = (i & 7) * 8;
        cp16h(Qs + r * APH + c, Q + (size_t)(b * SS + qt * 64 + r) * QKVS + c, 16);
    }

    auto ldkv = [&](int kt, int bf) {
#pragma unroll
        for (int j = 0; j < 4; j++) {
            int i = tid + j * 128;
            int r = i >> 3, c = (i & 7) * 8;
            cp16h(Ks + bf * 64 * APH + r * APH + c,
                  Kp + (size_t)(b * SS + kt * 64 + r) * QKVS + c, 16);
        }
#pragma unroll
        for (int j = 0; j < 4; j++) {
            int i = tid + j * 128;
            int r = i >> 3, c = (i & 7) * 8;
            cp16h(Vs + bf * 64 * APH + r * APH + c,
                  Vt + (size_t)r * SS + kt * 64 + c, 16);
        }
    };

    float oacc[8][4];
#pragma unroll
    for (int nf = 0; nf < 8; nf++)
#pragma unroll
        for (int i = 0; i < 4; i++) oacc[nf][i] = 0.f;
    float l0 = 0.f, l1 = 0.f;

    const int prow = wid * 16 + g;

    ldkv(0, 0);
    CP_COMMIT();

    for (int kt = 0; kt < SS / 64; kt++) {
        int bf = kt & 1;
        __syncthreads();
        if (kt + 1 < SS / 64) ldkv(kt + 1, bf ^ 1);
        CP_COMMIT();
        CP_WAIT1();
        __syncthreads();

        unsigned Kbu = Ku + (unsigned)(bf * 64 * APH) * 2u;
        unsigned Vbu = Vu + (unsigned)(bf * 64 * APH) * 2u;

        float sacc[8][4];
#pragma unroll
        for (int nf = 0; nf < 8; nf++)
#pragma unroll
            for (int i = 0; i < 4; i++) sacc[nf][i] = 0.f;
#pragma unroll
        for (int ks = 0; ks < 64; ks += 16) {
            unsigned a[4], bfr[8][2];
            ldsm4(a, Qu + (unsigned)((wid * 16 * APH + ks) + laneA) * 2u);
#pragma unroll
            for (int np = 0; np < 4; np++)
                ldsm4(&bfr[2 * np][0], Kbu + (unsigned)((np * 16 * APH + ks) + laneB) * 2u);
#pragma unroll
            for (int nf = 0; nf < 8; nf++)
                mma_bf16(sacc[nf], a, bfr[nf]);
        }

#pragma unroll
        for (int nf = 0; nf < 8; nf++) {
            float p0 = __expf(sacc[nf][0] * 0.125f);
            float p1 = __expf(sacc[nf][1] * 0.125f);
            float p2 = __expf(sacc[nf][2] * 0.125f);
            float p3 = __expf(sacc[nf][3] * 0.125f);
            l0 += p0 + p1; l1 += p2 + p3;
            *reinterpret_cast<bf162*>(Ps + prow * APH + nf * 8 + 2 * t) =
                __floats2bfloat162_rn(p0, p1);
            *reinterpret_cast<bf162*>(Ps + (prow + 8) * APH + nf * 8 + 2 * t) =
                __floats2bfloat162_rn(p2, p3);
        }
        __syncwarp();

#pragma unroll
        for (int ks = 0; ks < 64; ks += 16) {
            unsigned a[4], bfr[8][2];
            ldsm4(a, Pu + (unsigned)((wid * 16 * APH + ks) + laneA) * 2u);
#pragma unroll
            for (int np = 0; np < 4; np++)
                ldsm4(&bfr[2 * np][0], Vbu + (unsigned)((np * 16 * APH + ks) + laneB) * 2u);
#pragma unroll
            for (int nf = 0; nf < 8; nf++)
                mma_bf16(oacc[nf], a, bfr[nf]);
        }
    }

    l0 += __shfl_xor_sync(0xffffffffu, l0, 1);
    l0 += __shfl_xor_sync(0xffffffffu, l0, 2);
    l1 += __shfl_xor_sync(0xffffffffu, l1, 1);
    l1 += __shfl_xor_sync(0xffffffffu, l1, 2);
    float i0 = 1.f / l0, i1 = 1.f / l1;
    size_t rbase0 = ((size_t)(b * SS + qt * 64 + prow)) * HH + hoff;
    size_t rbase1 = rbase0 + (size_t)8 * HH;
#pragma unroll
    for (int nf = 0; nf < 8; nf++) {
        int c = nf * 8 + 2 * t;
        *reinterpret_cast<bf162*>(O + rbase0 + c) =
            __floats2bfloat162_rn(oacc[nf][0] * i0, oacc[nf][1] * i0);
        *reinterpret_cast<bf162*>(O + rbase1 + c) =
            __floats2bfloat162_rn(oacc[nf][2] * i1, oacc[nf][3] * i1);
    }
}

// ---------------- routing (fp32, exact) ----------------
__global__ void route_kernel(const float* __restrict__ y2,
                             const float* __restrict__ gw) {
    int t = blockIdx.x;
    int w = threadIdx.x >> 5, lane = threadIdx.x & 31;
    const float* xr = y2 + (size_t)t * HH;
    const float* gr = gw + (size_t)w * HH;
    float p = 0.f;
    for (int d = lane; d < HH; d += 32) p += xr[d] * gr[d];
#pragma unroll
    for (int o = 16; o > 0; o >>= 1) p += __shfl_down_sync(0xffffffffu, p, o);
    __shared__ float lg[EE];
    if (lane == 0) lg[w] = p;
    __syncthreads();
    if (threadIdx.x == 0) {
        int b0 = 0; float v0 = lg[0];
        for (int e = 1; e < EE; e++) if (lg[e] > v0) { v0 = lg[e]; b0 = e; }
        int b1 = -1; float v1 = -1e30f;
        for (int e = 0; e < EE; e++) {
            if (e == b0) continue;
            if (lg[e] > v1) { v1 = lg[e]; b1 = e; }
        }
        float ex = expf(v1 - v0);
        float den = 1.f / (1.f + ex);
        int p0 = atomicAdd(&g_cnt[b0], 1);
        g_tok[b0 * TT + p0] = t; g_wgt[b0 * TT + p0] = den;
        g_slot[2 * t] = b0 * TT + p0;
        int p1 = atomicAdd(&g_cnt[b1], 1);
        g_tok[b1 * TT + p1] = t; g_wgt[b1 * TT + p1] = ex * den;
        g_slot[2 * t + 1] = b1 * TT + p1;
    }
}

// ---------------- combine: out[t] += moe[slot0] + moe[slot1] ----------------
__global__ void combine_kernel(float* __restrict__ out,
                               const float* __restrict__ moe) {
    int t = blockIdx.x;
    int s0 = g_slot[2 * t], s1 = g_slot[2 * t + 1];
    int d = threadIdx.x * 4;
    float4 o = *reinterpret_cast<float4*>(out + (size_t)t * HH + d);
    float4 a = *reinterpret_cast<const float4*>(moe + (size_t)s0 * HH + d);
    float4 b = *reinterpret_cast<const float4*>(moe + (size_t)s1 * HH + d);
    o.x += a.x + b.x; o.y += a.y + b.y;
    o.z += a.z + b.z; o.w += a.w + b.w;
    *reinterpret_cast<float4*>(out + (size_t)t * HH + d) = o;
}

// ---------------- launch ----------------
extern "C" void kernel_launch(void* const* d_in, const int* in_sizes, int n_in,
                              void* d_out, int out_size) {
    const float* x   = (const float*)d_in[0];
    const float* ln1 = (const float*)d_in[1];
    const float* ln2 = (const float*)d_in[2];
    const float* wq  = (const float*)d_in[3];
    const float* wk  = (const float*)d_in[4];
    const float* wv  = (const float*)d_in[5];
    const float* wo  = (const float*)d_in[6];
    const float* gw  = (const float*)d_in[7];
    const float* w1  = (const float*)d_in[8];
    const float* w2  = (const float*)d_in[9];
    const float* w3  = (const float*)d_in[10];
    float* out = (float*)d_out;

    bf16 *y, *qkv, *wqkvh, *woh, *w1h, *w2h, *w3h, *vT, *att, *y2h, *h1, *h3;
    float *y2f, *moe;
    cudaGetSymbolAddress((void**)&y,     g_y);
    cudaGetSymbolAddress((void**)&qkv,   g_qkv);
    cudaGetSymbolAddress((void**)&wqkvh, g_wqkv);
    cudaGetSymbolAddress((void**)&woh,   g_woh);
    cudaGetSymbolAddress((void**)&w1h,   g_w1h);
    cudaGetSymbolAddress((void**)&w2h,   g_w2h);
    cudaGetSymbolAddress((void**)&w3h,   g_w3h);
    cudaGetSymbolAddress((void**)&vT,    g_vT);
    cudaGetSymbolAddress((void**)&att,   g_att);
    cudaGetSymbolAddress((void**)&y2h,   g_y2h);
    cudaGetSymbolAddress((void**)&y2f,   g_y2f);
    cudaGetSymbolAddress((void**)&h1,    g_h1);
    cudaGetSymbolAddress((void**)&h3,    g_h3);
    cudaGetSymbolAddress((void**)&moe,   g_moe);

    static int smem_set = 0;
    if (!smem_set) {
        cudaFuncSetAttribute(attn_tc,  cudaFuncAttributeMaxDynamicSharedMemorySize, ATTN_SMEM);
        cudaFuncSetAttribute(tgemm<1>, cudaFuncAttributeMaxDynamicSharedMemorySize, GEMM_SMEM);
        cudaFuncSetAttribute(tgemm<2>, cudaFuncAttributeMaxDynamicSharedMemorySize, GEMM_SMEM);
        cudaFuncSetAttribute(tgemm<3>, cudaFuncAttributeMaxDynamicSharedMemorySize, GEMM_SMEM);
        cudaFuncSetAttribute(tgemm<4>, cudaFuncAttributeMaxDynamicSharedMemorySize, GEMM_SMEM);
        cudaFuncSetAttribute(tgemm<5>, cudaFuncAttributeMaxDynamicSharedMemorySize, GEMM_SMEM);
        smem_set = 1;
    }

    zero_cnt_kernel<<<1, 32>>>();

    const int HW = HH * HH;          // 1,048,576
    const int EW = EE * II * HH;     // 16,777,216
    cvt_kernel<<<HW / 2048, 256>>>(wqkvh,          wq, HW);
    cvt_kernel<<<HW / 2048, 256>>>(wqkvh + HW,     wk, HW);
    cvt_kernel<<<HW / 2048, 256>>>(wqkvh + 2 * HW, wv, HW);
    cvt_kernel<<<HW / 2048, 256>>>(woh,            wo, HW);
    cvt_kernel<<<EW / 2048, 256>>>(w1h, w1, EW);
    cvt_kernel<<<EW / 2048, 256>>>(w2h, w2, EW);
    cvt_kernel<<<EW / 2048, 256>>>(w3h, w3, EW);

    // --- attention block ---
    rmsnorm_kernel<<<TT, 256>>>(x, ln1, y, nullptr);
    tgemm<4><<<dim3(TT / 128, QKVS / 128), 128, GEMM_SMEM>>>(y, wqkvh, qkv, vT, TT, QKVS, HH);
    attn_tc<<<dim3(SS / 64, NHH, BB), 128, ATTN_SMEM>>>(qkv, vT, att);
    tgemm<1><<<dim3(TT / 128, HH / 128), 128, GEMM_SMEM>>>(att, woh, out, x, TT, HH, HH);

    // --- MoE block ---
    rmsnorm_kernel<<<TT, 256>>>(out, ln2, y2h, y2f);
    route_kernel<<<TT, 256>>>(y2f, gw);
    tgemm<2><<<dim3(TT / 128, II / 128, EE), 128, GEMM_SMEM>>>(y2h, w1h, h1, nullptr, TT, II, HH);
    tgemm<5><<<dim3(TT / 128, II / 128, EE), 128, GEMM_SMEM>>>(y2h, w3h, h3, h1, TT, II, HH);
    tgemm<3><<<dim3(TT / 128, HH / 128, EE), 128, GEMM_SMEM>>>(h3, w2h, moe, nullptr, TT, HH, II);
    combine_kernel<<<TT, 256>>>(out, moe);
}